// round 1
// baseline (speedup 1.0000x reference)
#include <cuda_runtime.h>

#define H_N      1500
#define G4       6000
#define T_STEPS  4096
#define MLP_HID_N 1875
#define OUT_N    20
#define IN_N     20
#define NCTA     148
#define NTHREADS 1024
#define RC       36      // rows cached in smem per CTA
#define WPAD     1508    // padded row stride (floats) for conflict-free LDS.128
#define MAXROWS  44

// ---------------- device scratch (static: no allocations allowed) ----------------
__device__ float    g_xp[(size_t)T_STEPS * G4];   // 98.3 MB precomputed input projections
__device__ float    g_hbuf[2][1504];              // double-buffered hidden state
__device__ float    g_hid[MLP_HID_N];
__device__ unsigned g_count;                      // grid barrier (monotonic per launch)

// ---------------- init: reset barrier + h0 each launch (graph-replay safe) -------
__global__ void init_kernel() {
    int i = blockIdx.x * blockDim.x + threadIdx.x;
    if (i < 1504) { g_hbuf[0][i] = 0.f; g_hbuf[1][i] = 0.f; }
    if (i == 0) g_count = 0u;
}

// ---------------- x_proj[t][r] = b_ih[r]+b_hh[r] + input[t]·W_ih[r] --------------
__global__ void xproj_kernel(const float* __restrict__ inp,
                             const float* __restrict__ W_ih,
                             const float* __restrict__ b_ih,
                             const float* __restrict__ b_hh) {
    __shared__ float Wsm[256 * 21];   // padded stride 21: conflict-free
    __shared__ float bsm[256];
    __shared__ float insm[128 * IN_N];
    int tid = threadIdx.x;
    int r0 = blockIdx.x * 256;
    int t0 = blockIdx.y * 128;

    for (int i = tid; i < 256 * IN_N; i += 256) {
        int rr = i / IN_N, k = i % IN_N;
        int row = r0 + rr;
        Wsm[rr * 21 + k] = (row < G4) ? W_ih[row * IN_N + k] : 0.f;
    }
    {
        int row = r0 + tid;
        bsm[tid] = (row < G4) ? (b_ih[row] + b_hh[row]) : 0.f;
    }
    for (int i = tid; i < 128 * IN_N; i += 256)
        insm[i] = inp[t0 * IN_N + i];
    __syncthreads();

    int row = r0 + tid;
    if (row < G4) {
        const float* wrow = &Wsm[tid * 21];
        float bias = bsm[tid];
        for (int tt = 0; tt < 128; tt++) {
            const float* ir = &insm[tt * IN_N];
            float acc = bias;
            #pragma unroll
            for (int k = 0; k < IN_N; k++) acc += ir[k] * wrow[k];
            g_xp[(size_t)(t0 + tt) * G4 + row] = acc;
        }
    }
}

// ---------------- persistent LSTM recurrence ------------------------------------
__global__ void __launch_bounds__(NTHREADS, 1)
lstm_kernel(const float* __restrict__ W_hh) {
    extern __shared__ float smem[];
    float* W_s    = smem;                       // RC * WPAD
    float* h_s    = W_s + RC * WPAD;            // 1504
    float* part   = h_s + 1504;                 // MAXROWS * 33
    float* xp_s   = part + MAXROWS * 33;        // MAXROWS
    float* gate_s = xp_s + MAXROWS;             // MAXROWS
    float* c_s    = gate_s + MAXROWS;           // 16

    const int tid  = threadIdx.x;
    const int lane = tid & 31;
    const int w    = tid >> 5;
    const int b    = blockIdx.x;
    const int nu   = (b < 20) ? 11 : 10;                   // hidden units this CTA
    const int u0   = (b < 20) ? b * 11 : 220 + (b - 20) * 10;
    const int nrows = 4 * nu;                              // gate rows (40 or 44)

    // cache first RC rows of this CTA's W_hh slice into smem (fp32)
    for (int idx = tid; idx < RC * 375; idx += NTHREADS) {
        int lr = idx / 375, c4 = idx % 375;
        int grow = (lr / nu) * H_N + u0 + (lr % nu);
        *(float4*)&W_s[lr * WPAD + c4 * 4] =
            *(const float4*)&W_hh[(size_t)grow * H_N + c4 * 4];
    }
    if (tid < nu) c_s[tid] = 0.f;

    // static per-thread row assignments
    const int lr_lo = lane;                                // < 32 <= nrows always
    const float* wlo = &W_s[lr_lo * WPAD];                 // always cached
    const int lr_hi = 32 + lane;
    const bool has_hi = (lr_hi < nrows);
    const float* whi = wlo;                                // dummy
    if (has_hi) {
        int grow_hi = (lr_hi / nu) * H_N + u0 + (lr_hi % nu);
        whi = (lr_hi < RC) ? &W_s[lr_hi * WPAD]
                           : &W_hh[(size_t)grow_hi * H_N];
    }
    int xrow = 0;
    if (tid < nrows) xrow = (tid / nu) * H_N + u0 + (tid % nu);

    __syncthreads();

    for (int t = 0; t < T_STEPS; t++) {
        // fetch h (prev step) and this step's x_proj rows
        const float* hb = g_hbuf[t & 1];
        if (tid < 375)  *(float4*)&h_s[tid * 4] = *(const float4*)&hb[tid * 4];
        if (tid < nrows) xp_s[tid] = g_xp[(size_t)t * G4 + xrow];
        __syncthreads();

        // matvec: lane = row, warp = column chunk; h broadcast from smem
        float acc_lo = 0.f, acc_hi = 0.f;
        for (int c4 = w; c4 < 375; c4 += 32) {
            float4 hv = *(const float4*)&h_s[c4 * 4];
            float4 wl = *(const float4*)&wlo[c4 * 4];
            acc_lo += wl.x * hv.x + wl.y * hv.y + wl.z * hv.z + wl.w * hv.w;
            if (has_hi) {
                float4 wh = *(const float4*)&whi[c4 * 4];
                acc_hi += wh.x * hv.x + wh.y * hv.y + wh.z * hv.z + wh.w * hv.w;
            }
        }
        part[lr_lo * 33 + w] = acc_lo;
        if (has_hi) part[lr_hi * 33 + w] = acc_hi;
        __syncthreads();

        // cross-warp reduce: warp r handles row r
        for (int row = w; row < nrows; row += 32) {
            float v = part[row * 33 + lane];
            v += __shfl_xor_sync(0xffffffffu, v, 16);
            v += __shfl_xor_sync(0xffffffffu, v, 8);
            v += __shfl_xor_sync(0xffffffffu, v, 4);
            v += __shfl_xor_sync(0xffffffffu, v, 2);
            v += __shfl_xor_sync(0xffffffffu, v, 1);
            if (lane == 0) gate_s[row] = v + xp_s[row];
        }
        __syncthreads();

        // elementwise gate update for my units
        if (tid < nu) {
            float ig = 1.f / (1.f + __expf(-gate_s[tid]));
            float fg = 1.f / (1.f + __expf(-gate_s[nu + tid]));
            float gg = tanhf(gate_s[2 * nu + tid]);
            float og = 1.f / (1.f + __expf(-gate_s[3 * nu + tid]));
            float c = fg * c_s[tid] + ig * gg;
            c_s[tid] = c;
            g_hbuf[(t + 1) & 1][u0 + tid] = og * tanhf(c);
        }
        __syncthreads();

        // grid barrier (monotonic count, reset per launch by init_kernel)
        if (tid == 0) {
            __threadfence();
            atomicAdd(&g_count, 1u);
            unsigned target = (unsigned)NCTA * (unsigned)(t + 1);
            while (*(volatile unsigned*)&g_count < target) { }
            __threadfence();
        }
        __syncthreads();
    }
}

// ---------------- MLP head -------------------------------------------------------
__global__ void mlp1_kernel(const float* __restrict__ W1,
                            const float* __restrict__ b1) {
    int gw   = (blockIdx.x * blockDim.x + threadIdx.x) >> 5;
    int lane = threadIdx.x & 31;
    if (gw >= MLP_HID_N) return;
    const float* wr = &W1[(size_t)gw * H_N];
    const float* hv = g_hbuf[0];   // T even -> last h written to buf 0
    float acc = 0.f;
    for (int c4 = lane; c4 < 375; c4 += 32) {
        float4 wv = *(const float4*)&wr[c4 * 4];
        float4 h4 = *(const float4*)&hv[c4 * 4];
        acc += wv.x * h4.x + wv.y * h4.y + wv.z * h4.z + wv.w * h4.w;
    }
    acc += __shfl_xor_sync(0xffffffffu, acc, 16);
    acc += __shfl_xor_sync(0xffffffffu, acc, 8);
    acc += __shfl_xor_sync(0xffffffffu, acc, 4);
    acc += __shfl_xor_sync(0xffffffffu, acc, 2);
    acc += __shfl_xor_sync(0xffffffffu, acc, 1);
    if (lane == 0) g_hid[gw] = acc + b1[gw];
}

__global__ void mlp2_kernel(const float* __restrict__ W2,
                            const float* __restrict__ b2,
                            float* __restrict__ out) {
    int wrp  = threadIdx.x >> 5;
    int lane = threadIdx.x & 31;
    if (wrp >= OUT_N) return;
    const float* wr = &W2[(size_t)wrp * MLP_HID_N];
    float acc = 0.f;
    for (int c = lane; c < MLP_HID_N; c += 32)
        acc += wr[c] * g_hid[c];
    acc += __shfl_xor_sync(0xffffffffu, acc, 16);
    acc += __shfl_xor_sync(0xffffffffu, acc, 8);
    acc += __shfl_xor_sync(0xffffffffu, acc, 4);
    acc += __shfl_xor_sync(0xffffffffu, acc, 2);
    acc += __shfl_xor_sync(0xffffffffu, acc, 1);
    if (lane == 0) out[wrp] = acc + b2[wrp];
}

// ---------------- launch ---------------------------------------------------------
extern "C" void kernel_launch(void* const* d_in, const int* in_sizes, int n_in,
                              void* d_out, int out_size) {
    const float* inp  = (const float*)d_in[0];
    const float* W_ih = (const float*)d_in[1];
    const float* W_hh = (const float*)d_in[2];
    const float* b_ih = (const float*)d_in[3];
    const float* b_hh = (const float*)d_in[4];
    const float* W1   = (const float*)d_in[5];
    const float* b1   = (const float*)d_in[6];
    const float* W2   = (const float*)d_in[7];
    const float* b2   = (const float*)d_in[8];
    float* out = (float*)d_out;

    size_t smem_bytes = (size_t)(RC * WPAD + 1504 + MAXROWS * 33 + MAXROWS + MAXROWS + 16)
                        * sizeof(float);
    cudaFuncSetAttribute(lstm_kernel, cudaFuncAttributeMaxDynamicSharedMemorySize,
                         (int)smem_bytes);

    init_kernel<<<2, 1024>>>();
    xproj_kernel<<<dim3(24, 32), 256>>>(inp, W_ih, b_ih, b_hh);
    lstm_kernel<<<NCTA, NTHREADS, smem_bytes>>>(W_hh);
    mlp1_kernel<<<235, 256>>>(W1, b1);
    mlp2_kernel<<<1, 1024>>>(W2, b2, out);
}

// round 3
// speedup vs baseline: 1.6366x; 1.6366x over previous
#include <cuda_runtime.h>

#define H_N      1500
#define G4       6000
#define T_STEPS  4096
#define MLP_HID_N 1875
#define OUT_N    20
#define IN_N     20
#define NCTA     148
#define NTHREADS 512
#define NB_ROWS  12          // plane-B rows (smem)
#define WPAD_B   1508        // padded B row stride (floats)
#define MAXROWS  44
#define NCHUNK   24          // max float4 column-chunks per warp (375 = 7*24 + 9*23)

// ---------------- device scratch ----------------
__device__ float    g_xp[(size_t)T_STEPS * G4];
__device__ float    g_hbuf[2][1504];
__device__ float    g_hid[MLP_HID_N];
__device__ unsigned g_count;

#define FMA2(acc, a, b) \
    asm("fma.rn.f32x2 %0, %1, %2, %0;" : "+l"(acc) : "l"(a), "l"(b))

// ---------------- init ----------------
__global__ void init_kernel() {
    int i = blockIdx.x * blockDim.x + threadIdx.x;
    if (i < 1504) { g_hbuf[0][i] = 0.f; g_hbuf[1][i] = 0.f; }
    if (i == 0) g_count = 0u;
}

// ---------------- x_proj ----------------
__global__ void xproj_kernel(const float* __restrict__ inp,
                             const float* __restrict__ W_ih,
                             const float* __restrict__ b_ih,
                             const float* __restrict__ b_hh) {
    __shared__ float Wsm[256 * 21];
    __shared__ float bsm[256];
    __shared__ float insm[128 * IN_N];
    int tid = threadIdx.x;
    int r0 = blockIdx.x * 256;
    int t0 = blockIdx.y * 128;

    for (int i = tid; i < 256 * IN_N; i += 256) {
        int rr = i / IN_N, k = i % IN_N;
        int row = r0 + rr;
        Wsm[rr * 21 + k] = (row < G4) ? W_ih[row * IN_N + k] : 0.f;
    }
    {
        int row = r0 + tid;
        bsm[tid] = (row < G4) ? (b_ih[row] + b_hh[row]) : 0.f;
    }
    for (int i = tid; i < 128 * IN_N; i += 256)
        insm[i] = inp[t0 * IN_N + i];
    __syncthreads();

    int row = r0 + tid;
    if (row < G4) {
        const float* wrow = &Wsm[tid * 21];
        float bias = bsm[tid];
        for (int tt = 0; tt < 128; tt++) {
            const float* ir = &insm[tt * IN_N];
            float acc = bias;
            #pragma unroll
            for (int k = 0; k < IN_N; k++) acc += ir[k] * wrow[k];
            g_xp[(size_t)(t0 + tt) * G4 + row] = acc;
        }
    }
}

// ---------------- persistent LSTM ----------------
__global__ void __launch_bounds__(NTHREADS, 1)
lstm_kernel(const float* __restrict__ W_hh) {
    extern __shared__ float smem[];
    float* Wb_s  = smem;                         // NB_ROWS * WPAD_B
    float* h_s   = Wb_s + NB_ROWS * WPAD_B;      // 1504
    float* part  = h_s + 1504;                   // MAXROWS * 17
    float* xp_s  = part + MAXROWS * 17;          // MAXROWS
    float* c_s   = xp_s + MAXROWS;               // 16

    const int tid  = threadIdx.x;
    const int lane = tid & 31;
    const int w    = tid >> 5;
    const int b    = blockIdx.x;
    const int nu   = (b < 20) ? 11 : 10;
    const int u0   = (b < 20) ? b * 11 : 220 + (b - 20) * 10;
    const int nrows = 4 * nu;
    const int nA    = nrows - NB_ROWS;           // 32 or 28 plane-A rows

    // column-chunk range for this warp: warps 0-6 get 24 chunks, 7-15 get 23
    const int NK    = (w < 7) ? 24 : 23;
    const int start = (w < 7) ? w * 24 : 168 + (w - 7) * 23;

    // ---- preload plane-B weights (rows nA..nA+11) into smem, pads zeroed ----
    for (int idx = tid; idx < NB_ROWS * (WPAD_B / 4); idx += NTHREADS) {
        int r = idx / (WPAD_B / 4), c4 = idx % (WPAD_B / 4);
        float4 v = make_float4(0.f, 0.f, 0.f, 0.f);
        if (c4 < 375) {
            int lr = nA + r;
            int grow = (lr / nu) * H_N + u0 + (lr % nu);
            v = *(const float4*)&W_hh[(size_t)grow * H_N + c4 * 4];
        }
        *(float4*)&Wb_s[r * WPAD_B + c4 * 4] = v;
    }
    if (tid < nu) c_s[tid] = 0.f;

    // ---- preload plane-A weights (row = lane) into registers ----
    ulonglong2 wA[NCHUNK];
    {
        const float* wrowA = W_hh;
        bool haveA = (lane < nA);
        if (haveA) {
            int grow = (lane / nu) * H_N + u0 + (lane % nu);
            wrowA = &W_hh[(size_t)grow * H_N];
        }
        #pragma unroll
        for (int k = 0; k < NCHUNK; k++) {
            if (haveA && k < NK)
                wA[k] = *(const ulonglong2*)&wrowA[(start + k) * 4];
            else
                wA[k] = make_ulonglong2(0ull, 0ull);
        }
    }

    // plane-B: all lanes mirror rows (lane%12) to avoid divergence
    const float* wrowB = &Wb_s[(lane % NB_ROWS) * WPAD_B];

    int xrow = 0;
    if (tid < nrows) xrow = (tid / nu) * H_N + u0 + (tid % nu);

    __syncthreads();

    for (int t = 0; t < T_STEPS; t++) {
        // fetch h (prev step) and prefetch xp rows for this step
        const float* hb = g_hbuf[t & 1];
        float4 hv4;
        if (tid < 376) hv4 = *(const float4*)&hb[tid * 4];
        float xp_v = 0.f;
        if (tid < nrows) xp_v = g_xp[(size_t)t * G4 + xrow];
        if (tid < 376) *(float4*)&h_s[tid * 4] = hv4;
        __syncthreads();

        // ---- matvec: packed f32x2 FMAs ----
        // NOTE: k >= NK (tail chunk of 23-chunk warps) must contribute ZERO to
        // both planes. wA[k] is zeroed there; hv is forced to zero so the
        // plane-B accumulator doesn't double-count the next warp's columns.
        unsigned long long aA0 = 0ull, aA1 = 0ull, aB0 = 0ull, aB1 = 0ull;
        const float* hbase = &h_s[start * 4];
        #pragma unroll
        for (int k = 0; k < NCHUNK; k++) {
            ulonglong2 hv = (k < NK) ? *(const ulonglong2*)&hbase[k * 4]
                                     : make_ulonglong2(0ull, 0ull);
            FMA2(aA0, wA[k].x, hv.x);
            FMA2(aA1, wA[k].y, hv.y);
            ulonglong2 wb = (k < NK) ? *(const ulonglong2*)&wrowB[(start + k) * 4]
                                     : make_ulonglong2(0ull, 0ull);
            FMA2(aB0, wb.x, hv.x);
            FMA2(aB1, wb.y, hv.y);
        }
        float accA, accB;
        {
            float2 a0 = *(float2*)&aA0, a1 = *(float2*)&aA1;
            accA = (a0.x + a0.y) + (a1.x + a1.y);
            float2 b0 = *(float2*)&aB0, b1 = *(float2*)&aB1;
            accB = (b0.x + b0.y) + (b1.x + b1.y);
        }
        if (lane < nA) part[lane * 17 + w] = accA;
        if (lane < NB_ROWS) part[(nA + lane) * 17 + w] = accB;
        if (tid < nrows) xp_s[tid] = xp_v;
        __syncthreads();

        // ---- per-unit reduce + gates: warp u owns hidden unit u ----
        if (w < nu) {
            float g4v[4];
            #pragma unroll
            for (int gg = 0; gg < 4; gg++) {
                int row = gg * nu + w;
                float v = (lane < 16) ? part[row * 17 + lane] : 0.f;
                v += __shfl_xor_sync(0xffffffffu, v, 8);
                v += __shfl_xor_sync(0xffffffffu, v, 4);
                v += __shfl_xor_sync(0xffffffffu, v, 2);
                v += __shfl_xor_sync(0xffffffffu, v, 1);
                g4v[gg] = v + xp_s[row];
            }
            if (lane == 0) {
                float ig = 1.f / (1.f + __expf(-g4v[0]));
                float fg = 1.f / (1.f + __expf(-g4v[1]));
                float gg = tanhf(g4v[2]);
                float og = 1.f / (1.f + __expf(-g4v[3]));
                float c = fg * c_s[w] + ig * gg;
                c_s[w] = c;
                g_hbuf[(t + 1) & 1][u0 + w] = og * tanhf(c);
            }
        }
        __syncthreads();

        // ---- grid barrier: release/acquire, monotonic count ----
        if (tid == 0) {
            unsigned* cnt = &g_count;
            asm volatile("red.release.gpu.global.add.u32 [%0], 1;" :: "l"(cnt) : "memory");
            unsigned target = (unsigned)NCTA * (unsigned)(t + 1);
            unsigned v;
            do {
                asm volatile("ld.acquire.gpu.global.u32 %0, [%1];" : "=r"(v) : "l"(cnt) : "memory");
            } while (v < target);
        }
        __syncthreads();
    }
}

// ---------------- MLP head ----------------
__global__ void mlp1_kernel(const float* __restrict__ W1,
                            const float* __restrict__ b1) {
    int gw   = (blockIdx.x * blockDim.x + threadIdx.x) >> 5;
    int lane = threadIdx.x & 31;
    if (gw >= MLP_HID_N) return;
    const float* wr = &W1[(size_t)gw * H_N];
    const float* hv = g_hbuf[0];   // T even -> last h in buf 0
    float acc = 0.f;
    for (int c4 = lane; c4 < 375; c4 += 32) {
        float4 wv = *(const float4*)&wr[c4 * 4];
        float4 h4 = *(const float4*)&hv[c4 * 4];
        acc += wv.x * h4.x + wv.y * h4.y + wv.z * h4.z + wv.w * h4.w;
    }
    acc += __shfl_xor_sync(0xffffffffu, acc, 16);
    acc += __shfl_xor_sync(0xffffffffu, acc, 8);
    acc += __shfl_xor_sync(0xffffffffu, acc, 4);
    acc += __shfl_xor_sync(0xffffffffu, acc, 2);
    acc += __shfl_xor_sync(0xffffffffu, acc, 1);
    if (lane == 0) g_hid[gw] = acc + b1[gw];
}

__global__ void mlp2_kernel(const float* __restrict__ W2,
                            const float* __restrict__ b2,
                            float* __restrict__ out) {
    int wrp  = threadIdx.x >> 5;
    int lane = threadIdx.x & 31;
    if (wrp >= OUT_N) return;
    const float* wr = &W2[(size_t)wrp * MLP_HID_N];
    float acc = 0.f;
    for (int c = lane; c < MLP_HID_N; c += 32)
        acc += wr[c] * g_hid[c];
    acc += __shfl_xor_sync(0xffffffffu, acc, 16);
    acc += __shfl_xor_sync(0xffffffffu, acc, 8);
    acc += __shfl_xor_sync(0xffffffffu, acc, 4);
    acc += __shfl_xor_sync(0xffffffffu, acc, 2);
    acc += __shfl_xor_sync(0xffffffffu, acc, 1);
    if (lane == 0) out[wrp] = acc + b2[wrp];
}

// ---------------- launch ----------------
extern "C" void kernel_launch(void* const* d_in, const int* in_sizes, int n_in,
                              void* d_out, int out_size) {
    const float* inp  = (const float*)d_in[0];
    const float* W_ih = (const float*)d_in[1];
    const float* W_hh = (const float*)d_in[2];
    const float* b_ih = (const float*)d_in[3];
    const float* b_hh = (const float*)d_in[4];
    const float* W1   = (const float*)d_in[5];
    const float* b1   = (const float*)d_in[6];
    const float* W2   = (const float*)d_in[7];
    const float* b2   = (const float*)d_in[8];
    float* out = (float*)d_out;

    size_t smem_bytes = (size_t)(NB_ROWS * WPAD_B + 1504 + MAXROWS * 17 + MAXROWS + 16)
                        * sizeof(float);
    cudaFuncSetAttribute(lstm_kernel, cudaFuncAttributeMaxDynamicSharedMemorySize,
                         (int)smem_bytes);

    init_kernel<<<2, 1024>>>();
    xproj_kernel<<<dim3(24, 32), 256>>>(inp, W_ih, b_ih, b_hh);
    lstm_kernel<<<NCTA, NTHREADS, smem_bytes>>>(W_hh);
    mlp1_kernel<<<235, 256>>>(W1, b1);
    mlp2_kernel<<<1, 1024>>>(W2, b2, out);
}